// round 17
// baseline (speedup 1.0000x reference)
#include <cuda_runtime.h>
#include <cstddef>

#define WORDS   1000000
#define EMB_D   64
#define KTH     4
#define BATCH   8192

#define E_ELEMS   (WORDS * EMB_D)                // 64,000,000 (fits int)
#define B_ELEMS   (WORDS * KTH)                  // 4,000,000
#define TOT_ELEMS (E_ELEMS + B_ELEMS)            // 68,000,000
#define K_CH      (TOT_ELEMS / 4)                // 17,000,000 chunks
#define E_CH      (E_ELEMS / 4)                  // 16,000,000
#define RB        128
#define INVB      (1.0f / (float)BATCH)

#define TPB     256
#define UNROLL  8
#define CPB     (TPB * UNROLL)                   // 2048 chunks per block

// Per-block partials (fully overwritten each launch -> graph-replay safe).
__device__ float g_pw[RB][EMB_D];
__device__ float g_pb[RB][KTH];
__device__ int   g_pc[RB];
// Sync state; every word returns to 0 each launch -> graph-replay safe.
__device__ unsigned int g_ticket;
__device__ unsigned int g_flag;
__device__ unsigned int g_ack;

// ---------------------------------------------------------------------------
// Helpers (int32 indices throughout)
// ---------------------------------------------------------------------------
__device__ __forceinline__ float load_src(int s,
                                          const float* __restrict__ emb,
                                          const float* __restrict__ bia) {
    return (s < E_ELEMS) ? __ldg(emb + s) : __ldg(bia + (s - E_ELEMS));
}

__device__ __forceinline__ float4 load_chunk_cs(int k,
                                                const float* __restrict__ emb,
                                                const float* __restrict__ bia) {
    const float4* p = (k < E_CH)
        ? (reinterpret_cast<const float4*>(emb) + k)
        : (reinterpret_cast<const float4*>(bia) + (k - E_CH));
    return __ldcs(p);
}

// ---------------------------------------------------------------------------
// Reduce body (blocks 0..RB-1)
// ---------------------------------------------------------------------------
__device__ void reduce_body(const float* __restrict__ embed,
                            const float* __restrict__ bias,
                            const int*   __restrict__ ctx_id,
                            const int*   __restrict__ tgt,
                            const int*   __restrict__ lab) {
    __shared__ float s_ctx[EMB_D];
    __shared__ float s_bias[KTH];
    __shared__ float s_w[8][EMB_D];
    __shared__ float s_b[8][KTH];
    __shared__ int   s_c[8];

    const int tid = threadIdx.x;
    const int ctx = __ldg(ctx_id);
    if (tid < EMB_D) s_ctx[tid]  = __ldg(embed + (size_t)ctx * EMB_D + tid);
    if (tid < KTH)   s_bias[tid] = __ldg(bias  + (size_t)ctx * KTH + tid);
    __syncthreads();

    const int warp  = tid >> 5;
    const int lane  = tid & 31;
    const int gwarp = blockIdx.x * 8 + warp;
    const int twarps = RB * 8;

    const float2 c2 = reinterpret_cast<const float2*>(s_ctx)[lane];

    float wx = 0.0f, wy = 0.0f;
    float b0 = 0.0f, b1 = 0.0f, b2 = 0.0f, b3 = 0.0f;
    int corr = 0;

    for (int b = gwarp; b < BATCH; b += twarps) {
        const int t = __ldg(tgt + b);
        const float2 e2 =
            reinterpret_cast<const float2*>(embed + (size_t)t * EMB_D)[lane];
        float p = e2.x * c2.x + e2.y * c2.y;
        #pragma unroll
        for (int o = 16; o; o >>= 1) p += __shfl_xor_sync(0xffffffffu, p, o);
        const float dot = p;

        const int   L    = __ldg(lab + b);
        const float labf = (float)L;

        float taurow = 0.0f;
        int   plabel = KTH + 1;
        float tj[KTH];
        #pragma unroll
        for (int j = KTH - 1; j >= 0; j--) {
            const float db = dot - s_bias[j];
            if (db <= 0.0f) plabel = j + 1;
            const float yt  = (j < L) ? 1.0f : -1.0f;
            const float tau = (db * yt > 0.0f) ? 0.0f : labf;
            tj[j] = tau;
            taurow += tau;
        }
        if (lane == 0) {
            b0 += tj[0]; b1 += tj[1]; b2 += tj[2]; b3 += tj[3];
            if (plabel == L) corr++;
        }
        wx += taurow * e2.x;
        wy += taurow * e2.y;
    }

    s_w[warp][2 * lane]     = wx;
    s_w[warp][2 * lane + 1] = wy;
    if (lane == 0) {
        s_b[warp][0] = b0; s_b[warp][1] = b1; s_b[warp][2] = b2; s_b[warp][3] = b3;
        s_c[warp] = corr;
    }
    __syncthreads();

    if (tid < EMB_D) {
        float s = 0.0f;
        #pragma unroll
        for (int w = 0; w < 8; w++) s += s_w[w][tid];
        g_pw[blockIdx.x][tid] = s;
    }
    if (tid < KTH) {
        float s = 0.0f;
        #pragma unroll
        for (int w = 0; w < 8; w++) s += s_b[w][tid];
        g_pb[blockIdx.x][tid] = s;
    }
    if (tid == 0) {
        int s = 0;
        #pragma unroll
        for (int w = 0; w < 8; w++) s += s_c[w];
        g_pc[blockIdx.x] = s;
    }
}

// Merge the context-row correction into one register (consumer blocks only).
__device__ __forceinline__ void merge_elt(float& r, int idx,
                                          int wlo, int whi, int blo, int bhi,
                                          const float* s_w, const float* s_b) {
    if (idx >= wlo && idx < whi) r += s_w[idx - wlo] * INVB;
    if (idx >= blo && idx < bhi) r -= s_b[idx - blo] * INVB;
}

// Which block's output range contains element idx (idx >= 4).
__device__ __forceinline__ int blk_of(int idx) { return (idx - 4) / (4 * CPB); }

// ---------------------------------------------------------------------------
// Single fused kernel. One float4 store loop carries ALL bulk output traffic.
// ---------------------------------------------------------------------------
__global__ void __launch_bounds__(TPB, 4)
prank_main_kernel(const float* __restrict__ emb,
                  const float* __restrict__ bia,
                  const int*   __restrict__ ctx_id,
                  const int*   __restrict__ tgt,
                  const int*   __restrict__ lab,
                  float* __restrict__ out) {
    __shared__ float c_tw[4][EMB_D];
    __shared__ float c_w[EMB_D];
    __shared__ float c_pb[4][KTH];
    __shared__ int   c_pc[4];
    __shared__ float c_b[KTH];
    __shared__ int   c_c;

    const int tid  = threadIdx.x;
    const int lane = tid & 31;

    if (blockIdx.x < RB) {
        reduce_body(emb, bia, ctx_id, tgt, lab);
        __threadfence();                     // publish partials (RB blocks only)
        __syncthreads();
        if (tid == 0) {
            const unsigned int old = atomicAdd(&g_ticket, 1u);
            if (old == RB - 1u) {
                g_ticket = 0;                // replay-safe reset
                atomicExch(&g_flag, 1u);     // release
            }
        }
    }

    const int base = blockIdx.x * CPB + 1;

    // ---- load phase: 8 aligned LDG.128 in flight ----
    float4 B[UNROLL];
    float  prev[UNROLL];

    #pragma unroll
    for (int i = 0; i < UNROLL; i++) {
        int kk = base + i * TPB + tid;
        if (kk >= K_CH) kk = K_CH - 1;       // clamp keeps warp converged
        B[i] = load_chunk_cs(kk, emb, bia);
    }

    #pragma unroll
    for (int i = 0; i < UNROLL; i++) {
        prev[i] = __shfl_up_sync(0xffffffffu, B[i].w, 1);
        if (lane == 0) {
            int kk = base + i * TPB + tid;
            if (kk >= K_CH) kk = K_CH - 1;
            prev[i] = load_src(4 * kk - 1, emb, bia);
        }
    }

    // ---- consumer branch: <=3 blocks chip-wide merge corrections in-reg ----
    {
        const int ctx = __ldg(ctx_id);
        const int wlo = 1 + ctx * EMB_D,       whi = wlo + EMB_D;
        const int blo = 1 + E_ELEMS + ctx * KTH, bhi = blo + KTH;
        const int rlo = 4 * base;
        int rhi = rlo + 4 * CPB;
        if (rhi > 4 * K_CH) rhi = 4 * K_CH;

        const bool ov = (rlo < whi && rhi > wlo) || (rlo < bhi && rhi > blo);

        if (ov) {
            if (tid == 0) {
                while (atomicAdd(&g_flag, 0u) == 0u) { __nanosleep(64); }
            }
            __syncthreads();
            __threadfence();                 // acquire partials

            {
                const int g = tid >> 6;
                const int c = tid & 63;
                float acc = 0.0f;
                #pragma unroll
                for (int i = 0; i < RB / 4; i++)
                    acc += g_pw[g + 4 * i][c];
                c_tw[g][c] = acc;
            }
            if (tid < 128) {
                float4 v = reinterpret_cast<const float4*>(g_pb)[tid];
                int cc = g_pc[tid];
                #pragma unroll
                for (int o = 16; o; o >>= 1) {
                    v.x += __shfl_xor_sync(0xffffffffu, v.x, o);
                    v.y += __shfl_xor_sync(0xffffffffu, v.y, o);
                    v.z += __shfl_xor_sync(0xffffffffu, v.z, o);
                    v.w += __shfl_xor_sync(0xffffffffu, v.w, o);
                    cc  += __shfl_xor_sync(0xffffffffu, cc, o);
                }
                if (lane == 0) {
                    c_pb[tid >> 5][0] = v.x; c_pb[tid >> 5][1] = v.y;
                    c_pb[tid >> 5][2] = v.z; c_pb[tid >> 5][3] = v.w;
                    c_pc[tid >> 5] = cc;
                }
            }
            __syncthreads();
            if (tid < EMB_D)
                c_w[tid] = c_tw[0][tid] + c_tw[1][tid] + c_tw[2][tid] + c_tw[3][tid];
            if (tid >= 64 && tid < 64 + KTH) {
                const int j = tid - 64;
                c_b[j] = c_pb[0][j] + c_pb[1][j] + c_pb[2][j] + c_pb[3][j];
            }
            if (tid == 128)
                c_c = c_pc[0] + c_pc[1] + c_pc[2] + c_pc[3];
            __syncthreads();

            #pragma unroll
            for (int i = 0; i < UNROLL; i++) {
                const int kk = base + i * TPB + tid;
                if (kk < K_CH) {
                    const int s = 4 * kk;
                    merge_elt(prev[i], s,     wlo, whi, blo, bhi, c_w, c_b);
                    merge_elt(B[i].x,  s + 1, wlo, whi, blo, bhi, c_w, c_b);
                    merge_elt(B[i].y,  s + 2, wlo, whi, blo, bhi, c_w, c_b);
                    merge_elt(B[i].z,  s + 3, wlo, whi, blo, bhi, c_w, c_b);
                }
            }

            // Specials (owners).
            const int wo = (wlo > 4) ? wlo : 4;
            const bool is_w_owner = (wo >= rlo && wo < rhi);
            const bool is_b_owner = (blo >= rlo && blo < rhi);
            if (is_w_owner) {
                if (tid == 128) out[0] = (float)c_c * INVB;
                if (tid >= 129 && tid < 132) {
                    const int j = tid - 128;             // 1..3
                    float v = __ldg(emb + (j - 1));
                    if (j >= wlo && j < whi) v += c_w[j - wlo] * INVB; // ctx==0
                    out[j] = v;
                }
            }
            if (is_b_owner && tid == 133) {
                float v = __ldg(bia + B_ELEMS - 1);
                if (ctx == WORDS - 1) v -= c_b[KTH - 1] * INVB;
                out[TOT_ELEMS] = v;
            }

            // Ack; last consumer resets flag + ack (replay-safe).
            __syncthreads();
            if (tid == 0) {
                int wend = whi - 1;
                int bend = bhi - 1;
                if (bend > 4 * K_CH - 1) bend = 4 * K_CH - 1;
                const unsigned int C =
                    (unsigned int)((blk_of(wend) - blk_of(wo) + 1) +
                                   (blk_of(bend) - blk_of(blo) + 1));
                const unsigned int old = atomicAdd(&g_ack, 1u);
                if (old == C - 1u) {
                    g_ack = 0u;
                    __threadfence();
                    g_flag = 0u;
                }
            }
        }
    }

    // ---- the one and only bulk store loop: pure STG.128 ----
    #pragma unroll
    for (int i = 0; i < UNROLL; i++) {
        const int kk = base + i * TPB + tid;
        if (kk < K_CH) {
            __stcs(reinterpret_cast<float4*>(out) + kk,
                   make_float4(prev[i], B[i].x, B[i].y, B[i].z));
        }
    }
}

extern "C" void kernel_launch(void* const* d_in, const int* in_sizes, int n_in,
                              void* d_out, int out_size) {
    const float* in_embed = (const float*)d_in[0];
    const float* in_bias  = (const float*)d_in[1];
    const int*   ctx_id   = (const int*)d_in[2];
    const int*   tgt      = (const int*)d_in[3];
    const int*   lab      = (const int*)d_in[4];
    float* out = (float*)d_out;
    (void)n_in; (void)out_size; (void)in_sizes;

    const int nchunks = K_CH - 1;                        // chunks 1..K_CH-1
    const int blocks  = (nchunks + CPB - 1) / CPB;
    prank_main_kernel<<<blocks, TPB>>>(in_embed, in_bias, ctx_id, tgt, lab, out);
}